// round 13
// baseline (speedup 1.0000x reference)
#include <cuda_runtime.h>
#include <cuda_bf16.h>
#include <cstdint>
#include <cstddef>

#define NBND 400001
#define NATM 100000
#define HD   300
#define AF   133
#define BF   147
#define MAXNB 6
#define NUND 200001

// ---------------- scratch ---------------------------------------------------
__device__ float g_inp [(size_t)NBND * HD];
__device__ float g_msgA[(size_t)NBND * HD];
__device__ float g_msgB[(size_t)NBND * HD];
__device__ float g_amsg[(size_t)NATM * HD];
__device__ float g_hid [(size_t)NATM * HD];
__device__ double g_sum  [2][HD];
__device__ double g_sumsq[2][HD];
__device__ float g_scale[2][HD];
__device__ float g_shift[2][HD];

// pre-split, pre-transposed weights: g_B[n][kpad] = W[k][n], bf16 hi/lo, zero pad
__device__ __nv_bfloat16 g_Bi_hi[320 * 160], g_Bi_lo[320 * 160];   // W_i K=147 ->160
__device__ __nv_bfloat16 g_Bh_hi[320 * 320], g_Bh_lo[320 * 320];   // W_h K=300 ->320
__device__ __nv_bfloat16 g_Bo_hi[320 * 448], g_Bo_lo[320 * 448];   // W_o K=433 ->448

// ---------------- helpers -----------------------------------------------------
__device__ __forceinline__ void mma16816(float* c, const uint32_t* a,
                                         uint32_t b0, uint32_t b1) {
    asm volatile(
        "mma.sync.aligned.m16n8k16.row.col.f32.bf16.bf16.f32 "
        "{%0,%1,%2,%3}, {%4,%5,%6,%7}, {%8,%9}, {%0,%1,%2,%3};"
        : "+f"(c[0]), "+f"(c[1]), "+f"(c[2]), "+f"(c[3])
        : "r"(a[0]), "r"(a[1]), "r"(a[2]), "r"(a[3]), "r"(b0), "r"(b1));
}
__device__ __forceinline__ void ldm_x4(uint32_t& r0, uint32_t& r1,
                                       uint32_t& r2, uint32_t& r3, uint32_t addr) {
    asm volatile("ldmatrix.sync.aligned.m8n8.x4.shared.b16 {%0,%1,%2,%3}, [%4];"
                 : "=r"(r0), "=r"(r1), "=r"(r2), "=r"(r3) : "r"(addr));
}
__device__ __forceinline__ uint32_t pack_hi(float x, float y) {
    __nv_bfloat16 hx = __float2bfloat16(x), hy = __float2bfloat16(y);
    return (uint32_t)__bfloat16_as_ushort(hx) | ((uint32_t)__bfloat16_as_ushort(hy) << 16);
}
__device__ __forceinline__ uint32_t pack_lo(float x, float y) {
    __nv_bfloat16 hx = __float2bfloat16(x), hy = __float2bfloat16(y);
    __nv_bfloat16 lx = __float2bfloat16(x - __bfloat162float(hx));
    __nv_bfloat16 ly = __float2bfloat16(y - __bfloat162float(hy));
    return (uint32_t)__bfloat16_as_ushort(lx) | ((uint32_t)__bfloat16_as_ushort(ly) << 16);
}
__device__ __forceinline__ uint32_t smem_u32(const void* p) {
    uint32_t a;
    asm("{ .reg .u64 t; cvta.to.shared.u64 t, %1; cvt.u32.u64 %0, t; }" : "=r"(a) : "l"(p));
    return a;
}
__device__ __forceinline__ void cp16(uint32_t dst, const void* src) {
    asm volatile("cp.async.cg.shared.global [%0], [%1], 16;" :: "r"(dst), "l"(src));
}
__device__ __forceinline__ void cp_commit() {
    asm volatile("cp.async.commit_group;" ::: "memory");
}
__device__ __forceinline__ void cp_wait0() {
    asm volatile("cp.async.wait_group 0;" ::: "memory");
}

// ---------------- HMMA GEMM --------------------------------------------------
// C[M,300] = A[M,K] @ W[K,300]; CTA tile 128x320, 512 threads, 4m x 4n warps,
// warp tile 32x80, BK=32, 2-stage cp.async double buffer, ldmatrix fragment loads.
// MODE 1 A-gather uses DISTANCE-2 register prefetch (fa double buffer) so the
// random-DRAM gather latency is covered by a full chunk of MMA work.
// 3-term bf16 split: AhBh + AhBl + AlBh.
// MODE 0: A = f_bonds (K=147). out = acc
// MODE 1: A = amsg[b2a[r]] - maybe_relu(msgsrc[b2revb[r]]) (K=300). out = relu(inp+acc)
// MODE 2: A = concat(f_atoms, amsg) (K=433). out = relu(acc + bias)
constexpr int RSA = 80;                 // smem row stride bytes (40 bf16)
constexpr int OFF_AH = 0;               // 128*80 = 10240
constexpr int OFF_AL = 10240;
constexpr int OFF_BH = 20480;           // 320*80 = 25600
constexpr int OFF_BL = 46080;
constexpr int STAGE  = 71680;
constexpr int SMEM_TOTAL = 2 * STAGE;   // 143360

template <int MODE>
__global__ __launch_bounds__(512, 1) void tc_gemm(
    const float* __restrict__ A,
    const __nv_bfloat16* __restrict__ Bhi,
    const __nv_bfloat16* __restrict__ Blo,
    const float* __restrict__ inp,
    const float* __restrict__ amsg,
    const float* __restrict__ msgsrc,
    const int*   __restrict__ b2a,
    const int*   __restrict__ b2revb,
    const float* __restrict__ bias,
    float* __restrict__ out,
    int M, int relu_src)
{
    constexpr int K    = (MODE == 0) ? BF : (MODE == 1) ? HD : (AF + HD);
    constexpr int NC   = (K + 31) / 32;
    constexpr int KPAD = NC * 32;

    extern __shared__ char smem[];
    const uint32_t sbase = smem_u32(smem);
    const int tid = threadIdx.x;
    const int wid = tid >> 5, lid = tid & 31;
    const int wm = wid & 3, wn = wid >> 2;          // 4m x 4n warp grid
    const int grp = lid >> 2, thr = lid & 3;
    const int m0 = blockIdx.x * 128;

    // ldmatrix lane-address bases (within stage)
    const uint32_t offA = OFF_AH + (uint32_t)(wm * 32 + (lid & 15)) * RSA
                        + ((lid >> 4) & 1) * 16;
    const uint32_t offB = OFF_BH + (uint32_t)(wn * 80 + ((lid >> 4) & 1) * 8 + (lid & 7)) * RSA
                        + ((lid >> 3) & 1) * 16;

    // MODE1 gather pointers (4 threads per row)
    const float4* pa = nullptr; const float4* pb = nullptr;
    int rowvalid = 0;
    const int arow = tid >> 2;                 // 0..127
    const int kq   = (tid & 3) * 8;            // 0,8,16,24
    if (MODE == 1) {
        int gr = m0 + arow;
        rowvalid = (gr < M);
        int ia = rowvalid ? b2a[gr] : 0;
        int ib = rowvalid ? b2revb[gr] : 0;
        pa = (const float4*)(amsg   + (size_t)ia * HD);
        pb = (const float4*)(msgsrc + (size_t)ib * HD);
    }

    float acc[2][10][4];
#pragma unroll
    for (int mf = 0; mf < 2; mf++)
#pragma unroll
        for (int nf = 0; nf < 10; nf++)
#pragma unroll
            for (int q = 0; q < 4; q++) acc[mf][nf][q] = 0.f;

    // A prefetch registers: MODE1 uses fa as two 8-float buffers (chunk parity);
    // MODE0/2 use all 16 as a single distance-1 buffer.
    float fa[16];

    auto issueB = [&](int c, int buf) {
        const int k0 = c * 32;
        const uint32_t sb = sbase + buf * STAGE;
#pragma unroll
        for (int i = 0; i < 5; i++) {
            int idx = tid + i * 512;            // 2560 = 2 x 320 x 4
            int half = (idx >= 1280);
            int j = half ? idx - 1280 : idx;
            int n = j >> 2, g = j & 3;
            const __nv_bfloat16* src = (half ? Blo : Bhi) + (size_t)n * KPAD + k0 + g * 8;
            cp16(sb + (half ? OFF_BL : OFF_BH) + n * RSA + g * 16, src);
        }
    };
    auto loadA = [&](int c) {
        const int k0 = c * 32;
        if (MODE == 1) {
            float* f = fa + 8 * (c & 1);
#pragma unroll
            for (int j = 0; j < 2; j++) {
                int k = k0 + kq + j * 4;
                float4 v = {0.f, 0.f, 0.f, 0.f};
                if (rowvalid && k + 3 < HD) {
                    float4 x = pa[k >> 2], y = pb[k >> 2];
                    if (relu_src) {
                        y.x = fmaxf(y.x, 0.f); y.y = fmaxf(y.y, 0.f);
                        y.z = fmaxf(y.z, 0.f); y.w = fmaxf(y.w, 0.f);
                    }
                    v.x = x.x - y.x; v.y = x.y - y.y; v.z = x.z - y.z; v.w = x.w - y.w;
                }
                f[j * 4 + 0] = v.x; f[j * 4 + 1] = v.y;
                f[j * 4 + 2] = v.z; f[j * 4 + 3] = v.w;
            }
        } else {
#pragma unroll
            for (int i = 0; i < 8; i++) {
                int idx = tid + i * 512;        // 128*32 = 4096
                int r = idx >> 5, kl = idx & 31;
                int gr = m0 + r, k = k0 + kl;
                float v = 0.f;
                if (gr < M) {
                    if (MODE == 0) { if (k < BF) v = A[(size_t)gr * BF + k]; }
                    else {
                        if (k < AF) v = A[(size_t)gr * AF + k];
                        else if (k < AF + HD) v = amsg[(size_t)gr * HD + (k - AF)];
                    }
                }
                fa[i] = v;
            }
        }
    };
    auto storeA = [&](int c) {
        char* st = smem + (c & 1) * STAGE;
        if (MODE == 1) {
            const float* f = fa + 8 * (c & 1);
            char* dh = st + OFF_AH + arow * RSA + kq * 2;
            char* dl = st + OFF_AL + arow * RSA + kq * 2;
#pragma unroll
            for (int j = 0; j < 4; j++) {
                float x = f[j * 2], y = f[j * 2 + 1];
                *(uint32_t*)(dh + j * 4) = pack_hi(x, y);
                *(uint32_t*)(dl + j * 4) = pack_lo(x, y);
            }
        } else {
#pragma unroll
            for (int i = 0; i < 8; i++) {
                int idx = tid + i * 512;
                int r = idx >> 5, kl = idx & 31;
                float v = fa[i];
                __nv_bfloat16 h = __float2bfloat16(v);
                __nv_bfloat16 l = __float2bfloat16(v - __bfloat162float(h));
                *(__nv_bfloat16*)(st + OFF_AH + r * RSA + kl * 2) = h;
                *(__nv_bfloat16*)(st + OFF_AL + r * RSA + kl * 2) = l;
            }
        }
    };

    // ---- prologue ----
    loadA(0);
    storeA(0);
    issueB(0, 0);
    cp_commit();
    if (MODE == 1 && NC > 1) loadA(1);
    cp_wait0();
    __syncthreads();

    for (int c = 0; c < NC; c++) {
        const int cur = c & 1;
        const bool more = (c + 1 < NC);
        if (MODE == 1) {
            if (more) { storeA(c + 1); issueB(c + 1, cur ^ 1); cp_commit(); }
            if (c + 2 < NC) loadA(c + 2);
        } else {
            if (more) { issueB(c + 1, cur ^ 1); cp_commit(); loadA(c + 1); }
        }

        const uint32_t stb = sbase + cur * STAGE;
#pragma unroll
        for (int s = 0; s < 2; s++) {
            const uint32_t s32 = s * 32;
            uint32_t ah[2][4], al[2][4];
#pragma unroll
            for (int mf = 0; mf < 2; mf++) {
                ldm_x4(ah[mf][0], ah[mf][1], ah[mf][2], ah[mf][3],
                       stb + offA + mf * (16 * RSA) + s32);
                ldm_x4(al[mf][0], al[mf][1], al[mf][2], al[mf][3],
                       stb + offA + mf * (16 * RSA) + (OFF_AL - OFF_AH) + s32);
            }
#pragma unroll
            for (int p = 0; p < 5; p++) {
                uint32_t bh0a, bh1a, bh0b, bh1b;
                uint32_t bl0a, bl1a, bl0b, bl1b;
                ldm_x4(bh0a, bh1a, bh0b, bh1b, stb + offB + p * (16 * RSA) + s32);
                ldm_x4(bl0a, bl1a, bl0b, bl1b,
                       stb + offB + p * (16 * RSA) + (OFF_BL - OFF_BH) + s32);
#pragma unroll
                for (int mf = 0; mf < 2; mf++) {
                    mma16816(acc[mf][2 * p],     ah[mf], bh0a, bh1a);
                    mma16816(acc[mf][2 * p],     ah[mf], bl0a, bl1a);
                    mma16816(acc[mf][2 * p],     al[mf], bh0a, bh1a);
                    mma16816(acc[mf][2 * p + 1], ah[mf], bh0b, bh1b);
                    mma16816(acc[mf][2 * p + 1], ah[mf], bl0b, bl1b);
                    mma16816(acc[mf][2 * p + 1], al[mf], bh0b, bh1b);
                }
            }
        }
        if (MODE != 1 && more) storeA(c + 1);
        cp_wait0();
        __syncthreads();
    }

    // ---- epilogue ----
#pragma unroll
    for (int mf = 0; mf < 2; mf++) {
#pragma unroll
        for (int nf = 0; nf < 10; nf++) {
            int col = wn * 80 + nf * 8 + thr * 2;
            if (col >= HD) continue;
            int row0 = m0 + wm * 32 + mf * 16 + grp;
#pragma unroll
            for (int h = 0; h < 2; h++) {
                int r = row0 + h * 8;
                if (r >= M) continue;
                size_t o = (size_t)r * HD + col;
                float vx = acc[mf][nf][h * 2 + 0];
                float vy = acc[mf][nf][h * 2 + 1];
                if (MODE == 0) {
                    *(float2*)(out + o) = make_float2(vx, vy);
                } else if (MODE == 1) {
                    float2 p = *(const float2*)(inp + o);
                    *(float2*)(out + o) = make_float2(fmaxf(p.x + vx, 0.f),
                                                      fmaxf(p.y + vy, 0.f));
                } else {
                    *(float2*)(out + o) = make_float2(fmaxf(vx + bias[col], 0.f),
                                                      fmaxf(vy + bias[col + 1], 0.f));
                }
            }
        }
    }
}

// ---------------- fused prep: zero stats + split/transpose all weights --------
__global__ void prep_kernel(const float* __restrict__ W_i,
                            const float* __restrict__ W_h,
                            const float* __restrict__ W_o)
{
    const int S1 = 320 * 160, S2 = 320 * 320, S3 = 320 * 448;
    int idx = blockIdx.x * blockDim.x + threadIdx.x;
    if (idx < 2 * HD) {
        (&g_sum[0][0])[idx]   = 0.0;
        (&g_sumsq[0][0])[idx] = 0.0;
    }
    int t = idx - 600;
    if (t < 0) return;
    const float* W; __nv_bfloat16 *hi, *lo; int K, kpad;
    if (t < S1)            { W = W_i; hi = g_Bi_hi; lo = g_Bi_lo; K = BF;      kpad = 160; }
    else if (t < S1 + S2)  { t -= S1; W = W_h; hi = g_Bh_hi; lo = g_Bh_lo; K = HD; kpad = 320; }
    else if (t < S1+S2+S3) { t -= S1 + S2; W = W_o; hi = g_Bo_hi; lo = g_Bo_lo; K = AF + HD; kpad = 448; }
    else return;
    int n = t / kpad, k = t % kpad;
    float v = (n < HD && k < K) ? W[(size_t)k * HD + n] : 0.f;
    __nv_bfloat16 h = __float2bfloat16(v);
    hi[t] = h;
    lo[t] = __float2bfloat16(v - __bfloat162float(h));
}

// ---------------- aggregation -------------------------------------------------
__global__ void agg_kernel(const float* __restrict__ msg,
                           const int* __restrict__ a2b,
                           float* __restrict__ amsg, int do_relu)
{
    int idx = blockIdx.x * blockDim.x + threadIdx.x;
    if (idx >= NATM * 75) return;
    int i = idx / 75, k4 = idx % 75;
    float4 s = {0.f, 0.f, 0.f, 0.f};
#pragma unroll
    for (int j = 0; j < MAXNB; j++) {
        int b = __ldg(a2b + i * MAXNB + j);
        float4 v = *(const float4*)(msg + (size_t)b * HD + k4 * 4);
        if (do_relu) {
            v.x = fmaxf(v.x, 0.f); v.y = fmaxf(v.y, 0.f);
            v.z = fmaxf(v.z, 0.f); v.w = fmaxf(v.w, 0.f);
        }
        s.x += v.x; s.y += v.y; s.z += v.z; s.w += v.w;
    }
    *(float4*)(amsg + (size_t)i * HD + k4 * 4) = s;
}

// ---------------- batchnorm (two-pass, fp64 accumulation) ---------------------
__global__ void stats_kernel(const float* __restrict__ x, int rows,
                             double* __restrict__ sum, double* __restrict__ sumsq)
{
    int c = threadIdx.x;
    if (c >= HD) return;
    long r0 = (long)blockIdx.x * 512;
    long r1 = r0 + 512; if (r1 > rows) r1 = rows;
    double s = 0.0, s2 = 0.0;
    for (long r = r0; r < r1; r++) {
        double v = (double)x[(size_t)r * HD + c];
        s += v; s2 += v * v;
    }
    atomicAdd(&sum[c], s);
    atomicAdd(&sumsq[c], s2);
}

__global__ void stats_und_kernel(const float* __restrict__ msg,
                                 double* __restrict__ sum, double* __restrict__ sumsq)
{
    int c = threadIdx.x;
    if (c >= HD) return;
    long r0 = (long)blockIdx.x * 512 + 1;
    long r1 = r0 + 512; if (r1 > NUND) r1 = NUND;
    double s = 0.0, s2 = 0.0;
    for (long r = r0; r < r1; r++) {
        float v = 0.5f * (msg[(size_t)(2 * r) * HD + c] + msg[(size_t)(2 * r - 1) * HD + c]);
        double d = (double)v;
        s += d; s2 += d * d;
    }
    atomicAdd(&sum[c], s);
    atomicAdd(&sumsq[c], s2);
}

__global__ void finalize_stats(int rowsA, int rowsB,
                               const float* __restrict__ gamma,
                               const float* __restrict__ beta)
{
    int t = blockIdx.x * blockDim.x + threadIdx.x;
    if (t >= 2 * HD) return;
    int g = t / HD, c = t % HD;
    long rows = g ? rowsB : rowsA;
    double mu  = g_sum[g][c] / rows;
    double var = g_sumsq[g][c] / rows - mu * mu;
    double sc  = (double)gamma[c] / sqrt(var + 1e-5);
    g_scale[g][c] = (float)sc;
    g_shift[g][c] = beta[c] - (float)(mu * sc);
}

__global__ void norm_kernel(const float* __restrict__ x, long rows, int grp,
                            float* __restrict__ out)
{
    long idx = (long)blockIdx.x * blockDim.x + threadIdx.x;
    if (idx >= rows * 75) return;
    int c4 = (int)(idx % 75);
    float4 v  = *(const float4*)(x + idx * 4);
    float4 sc = *(const float4*)(&g_scale[grp][c4 * 4]);
    float4 sh = *(const float4*)(&g_shift[grp][c4 * 4]);
    float4 o;
    o.x = v.x * sc.x + sh.x; o.y = v.y * sc.y + sh.y;
    o.z = v.z * sc.z + sh.z; o.w = v.w * sc.w + sh.w;
    *(float4*)(out + idx * 4) = o;
}

__global__ void norm_und_kernel(const float* __restrict__ msg, float* __restrict__ out)
{
    long idx = (long)blockIdx.x * blockDim.x + threadIdx.x;
    if (idx >= (long)(NUND - 1) * 75) return;
    long r = idx / 75 + 1;
    int c4 = (int)(idx % 75);
    float4 a = *(const float4*)(msg + (size_t)(2 * r) * HD + c4 * 4);
    float4 b = *(const float4*)(msg + (size_t)(2 * r - 1) * HD + c4 * 4);
    float4 sc = *(const float4*)(&g_scale[1][c4 * 4]);
    float4 sh = *(const float4*)(&g_shift[1][c4 * 4]);
    float4 o;
    o.x = 0.5f * (a.x + b.x) * sc.x + sh.x;
    o.y = 0.5f * (a.y + b.y) * sc.y + sh.y;
    o.z = 0.5f * (a.z + b.z) * sc.z + sh.z;
    o.w = 0.5f * (a.w + b.w) * sc.w + sh.w;
    *(float4*)(out + idx * 4) = o;
}

// ---------------- launch ------------------------------------------------------
extern "C" void kernel_launch(void* const* d_in, const int* in_sizes, int n_in,
                              void* d_out, int out_size)
{
    const float* f_atoms = (const float*)d_in[0];
    const float* f_bonds = (const float*)d_in[1];
    const int*   a2b     = (const int*)  d_in[2];
    const int*   b2a     = (const int*)  d_in[3];
    const int*   b2revb  = (const int*)  d_in[4];
    const float* W_i     = (const float*)d_in[5];
    const float* W_h     = (const float*)d_in[6];
    const float* W_o     = (const float*)d_in[7];
    const float* b_o     = (const float*)d_in[8];
    const float* gamma   = (const float*)d_in[9];
    const float* beta    = (const float*)d_in[10];

    float *inp, *msgA, *msgB, *amsg, *hid;
    double *sum, *sumsq;
    __nv_bfloat16 *bi_h, *bi_l, *bh_h, *bh_l, *bo_h, *bo_l;
    cudaGetSymbolAddress((void**)&inp,  g_inp);
    cudaGetSymbolAddress((void**)&msgA, g_msgA);
    cudaGetSymbolAddress((void**)&msgB, g_msgB);
    cudaGetSymbolAddress((void**)&amsg, g_amsg);
    cudaGetSymbolAddress((void**)&hid,  g_hid);
    cudaGetSymbolAddress((void**)&sum,  g_sum);
    cudaGetSymbolAddress((void**)&sumsq,g_sumsq);
    cudaGetSymbolAddress((void**)&bi_h, g_Bi_hi);
    cudaGetSymbolAddress((void**)&bi_l, g_Bi_lo);
    cudaGetSymbolAddress((void**)&bh_h, g_Bh_hi);
    cudaGetSymbolAddress((void**)&bh_l, g_Bh_lo);
    cudaGetSymbolAddress((void**)&bo_h, g_Bo_hi);
    cudaGetSymbolAddress((void**)&bo_l, g_Bo_lo);

    cudaFuncSetAttribute(tc_gemm<0>, cudaFuncAttributeMaxDynamicSharedMemorySize, SMEM_TOTAL);
    cudaFuncSetAttribute(tc_gemm<1>, cudaFuncAttributeMaxDynamicSharedMemorySize, SMEM_TOTAL);
    cudaFuncSetAttribute(tc_gemm<2>, cudaFuncAttributeMaxDynamicSharedMemorySize, SMEM_TOTAL);

    // launches: 0 prep | 1 gemm0 | 2 agg | 3 gemm1 | 4 agg | 5 gemm1 (ncu -s 5)
    prep_kernel<<<(600 + 320 * (160 + 320 + 448) + 255) / 256, 256>>>(W_i, W_h, W_o);

    dim3 gB((NBND + 127) / 128);   // 3126
    dim3 gO((NATM + 127) / 128);   // 782
    const int AGG_G = (NATM * 75 + 255) / 256;

    tc_gemm<0><<<gB, 512, SMEM_TOTAL>>>(f_bonds, bi_h, bi_l, nullptr, nullptr, nullptr,
                                        nullptr, nullptr, nullptr, inp, NBND, 0);
    agg_kernel<<<AGG_G, 256>>>(inp, a2b, amsg, 1);
    tc_gemm<1><<<gB, 512, SMEM_TOTAL>>>(nullptr, bh_h, bh_l, inp, amsg, inp,
                                        b2a, b2revb, nullptr, msgB, NBND, 1);
    agg_kernel<<<AGG_G, 256>>>(msgB, a2b, amsg, 0);
    tc_gemm<1><<<gB, 512, SMEM_TOTAL>>>(nullptr, bh_h, bh_l, inp, amsg, msgB,
                                        b2a, b2revb, nullptr, msgA, NBND, 0);
    agg_kernel<<<AGG_G, 256>>>(msgA, a2b, amsg, 0);
    tc_gemm<2><<<gO, 512, SMEM_TOTAL>>>(f_atoms, bo_h, bo_l, nullptr, amsg, nullptr,
                                        nullptr, nullptr, b_o, hid, NATM, 0);

    stats_kernel<<<(NATM - 1 + 511) / 512, 320>>>(hid + HD, NATM - 1, sum, sumsq);
    stats_und_kernel<<<(NUND - 1 + 511) / 512, 320>>>(msgA, sum + HD, sumsq + HD);
    finalize_stats<<<(2 * HD + 255) / 256, 256>>>(NATM - 1, NUND - 1, gamma, beta);

    float* outp = (float*)d_out;
    long nAtom4 = (long)(NATM - 1) * 75;
    long nBond4 = (long)(NUND - 1) * 75;
    norm_kernel<<<(int)((nAtom4 + 255) / 256), 256>>>(hid + HD, NATM - 1, 0, outp);
    norm_und_kernel<<<(int)((nBond4 + 255) / 256), 256>>>(msgA, outp + nAtom4 * 4);
}

// round 14
// speedup vs baseline: 1.3541x; 1.3541x over previous
#include <cuda_runtime.h>
#include <cuda_bf16.h>
#include <cstdint>
#include <cstddef>

#define NBND 400001
#define NATM 100000
#define HD   300
#define AF   133
#define BF   147
#define MAXNB 6
#define NUND 200001
#define KP   320          // padded K / row stride for bf16 msg arrays

// ---------------- scratch ---------------------------------------------------
__device__ float g_inp [(size_t)NBND * HD];     // pre-relu input messages
__device__ float g_P   [(size_t)NBND * HD];     // P = msg @ W_h
__device__ float g_msgF[(size_t)NBND * HD];     // final message (fp32)
__device__ __nv_bfloat16 g_msgH[(size_t)NBND * KP];   // msg hi (320-padded)
__device__ __nv_bfloat16 g_msgL[(size_t)NBND * KP];   // msg lo
__device__ float g_amsg[(size_t)NATM * HD];     // aP / amsg
__device__ float g_hid [(size_t)NATM * HD];
__device__ double g_sum  [2][HD];
__device__ double g_sumsq[2][HD];
__device__ float g_scale[2][HD];
__device__ float g_shift[2][HD];

// pre-split, pre-transposed weights: g_B[n][kpad] = W[k][n], bf16 hi/lo, zero pad
__device__ __nv_bfloat16 g_Bi_hi[320 * 160], g_Bi_lo[320 * 160];   // W_i K=147 ->160
__device__ __nv_bfloat16 g_Bh_hi[320 * 320], g_Bh_lo[320 * 320];   // W_h K=300 ->320
__device__ __nv_bfloat16 g_Bo_hi[320 * 448], g_Bo_lo[320 * 448];   // W_o K=433 ->448

// ---------------- helpers -----------------------------------------------------
__device__ __forceinline__ void mma16816(float* c, const uint32_t* a,
                                         uint32_t b0, uint32_t b1) {
    asm volatile(
        "mma.sync.aligned.m16n8k16.row.col.f32.bf16.bf16.f32 "
        "{%0,%1,%2,%3}, {%4,%5,%6,%7}, {%8,%9}, {%0,%1,%2,%3};"
        : "+f"(c[0]), "+f"(c[1]), "+f"(c[2]), "+f"(c[3])
        : "r"(a[0]), "r"(a[1]), "r"(a[2]), "r"(a[3]), "r"(b0), "r"(b1));
}
__device__ __forceinline__ void ldm_x4(uint32_t& r0, uint32_t& r1,
                                       uint32_t& r2, uint32_t& r3, uint32_t addr) {
    asm volatile("ldmatrix.sync.aligned.m8n8.x4.shared.b16 {%0,%1,%2,%3}, [%4];"
                 : "=r"(r0), "=r"(r1), "=r"(r2), "=r"(r3) : "r"(addr));
}
__device__ __forceinline__ uint32_t pack_hi(float x, float y) {
    __nv_bfloat16 hx = __float2bfloat16(x), hy = __float2bfloat16(y);
    return (uint32_t)__bfloat16_as_ushort(hx) | ((uint32_t)__bfloat16_as_ushort(hy) << 16);
}
__device__ __forceinline__ uint32_t pack_lo(float x, float y) {
    __nv_bfloat16 hx = __float2bfloat16(x), hy = __float2bfloat16(y);
    __nv_bfloat16 lx = __float2bfloat16(x - __bfloat162float(hx));
    __nv_bfloat16 ly = __float2bfloat16(y - __bfloat162float(hy));
    return (uint32_t)__bfloat16_as_ushort(lx) | ((uint32_t)__bfloat16_as_ushort(ly) << 16);
}
__device__ __forceinline__ uint32_t smem_u32(const void* p) {
    uint32_t a;
    asm("{ .reg .u64 t; cvta.to.shared.u64 t, %1; cvt.u32.u64 %0, t; }" : "=r"(a) : "l"(p));
    return a;
}
__device__ __forceinline__ void cp16(uint32_t dst, const void* src) {
    asm volatile("cp.async.cg.shared.global [%0], [%1], 16;" :: "r"(dst), "l"(src));
}
__device__ __forceinline__ void cp_commit() {
    asm volatile("cp.async.commit_group;" ::: "memory");
}
__device__ __forceinline__ void cp_wait0() {
    asm volatile("cp.async.wait_group 0;" ::: "memory");
}

// ---------------- shared GEMM geometry ----------------------------------------
constexpr int RSA = 80;
constexpr int OFF_AH = 0;               // 128*80 = 10240
constexpr int OFF_AL = 10240;
constexpr int OFF_BH = 20480;           // 320*80 = 25600
constexpr int OFF_BL = 46080;
constexpr int STAGE  = 71680;
constexpr int SMEM_TOTAL = 2 * STAGE;   // 143360

// ---------------- dense bf16 GEMM: P[M,300] = msg(hi/lo) @ W ------------------
// A pre-split bf16 [M, KP]; all operands via cp.async; pure MMA mainloop.
__global__ __launch_bounds__(512, 1) void tc_gemm_dense(
    const __nv_bfloat16* __restrict__ Ah,
    const __nv_bfloat16* __restrict__ Al,
    const __nv_bfloat16* __restrict__ Bhi,
    const __nv_bfloat16* __restrict__ Blo,
    float* __restrict__ out, int M)
{
    constexpr int NC = 10;              // K = 300 -> 320
    extern __shared__ char smem[];
    const uint32_t sbase = smem_u32(smem);
    const int tid = threadIdx.x;
    const int wid = tid >> 5, lid = tid & 31;
    const int wm = wid & 3, wn = wid >> 2;
    const int grp = lid >> 2, thr = lid & 3;
    const int m0 = blockIdx.x * 128;

    const uint32_t offA = OFF_AH + (uint32_t)(wm * 32 + (lid & 15)) * RSA
                        + ((lid >> 4) & 1) * 16;
    const uint32_t offB = OFF_BH + (uint32_t)(wn * 80 + ((lid >> 4) & 1) * 8 + (lid & 7)) * RSA
                        + ((lid >> 3) & 1) * 16;

    float acc[2][10][4];
#pragma unroll
    for (int mf = 0; mf < 2; mf++)
#pragma unroll
        for (int nf = 0; nf < 10; nf++)
#pragma unroll
            for (int q = 0; q < 4; q++) acc[mf][nf][q] = 0.f;

    auto issueAll = [&](int c, int buf) {
        const int k0 = c * 32;
        const uint32_t sb = sbase + buf * STAGE;
        // A hi/lo: 1024 cp16 (128 rows x 4 chunks x 2)
#pragma unroll
        for (int i = 0; i < 2; i++) {
            int id = tid + i * 512;
            int half = (id >= 512);
            int j = id & 511;
            int r = j >> 2, g = j & 3;
            int rg = m0 + r; if (rg >= M) rg = 0;
            const __nv_bfloat16* src = (half ? Al : Ah) + (size_t)rg * KP + k0 + g * 8;
            cp16(sb + (half ? OFF_AL : OFF_AH) + r * RSA + g * 16, src);
        }
        // B hi/lo: 2560 cp16
#pragma unroll
        for (int i = 0; i < 5; i++) {
            int idx = tid + i * 512;
            int half = (idx >= 1280);
            int j = half ? idx - 1280 : idx;
            int n = j >> 2, g = j & 3;
            const __nv_bfloat16* src = (half ? Blo : Bhi) + (size_t)n * KP + k0 + g * 8;
            cp16(sb + (half ? OFF_BL : OFF_BH) + n * RSA + g * 16, src);
        }
        cp_commit();
    };

    issueAll(0, 0);
    cp_wait0();
    __syncthreads();

    for (int c = 0; c < NC; c++) {
        const int cur = c & 1;
        if (c + 1 < NC) issueAll(c + 1, cur ^ 1);

        const uint32_t stb = sbase + cur * STAGE;
#pragma unroll
        for (int s = 0; s < 2; s++) {
            const uint32_t s32 = s * 32;
            uint32_t ah[2][4], al[2][4];
#pragma unroll
            for (int mf = 0; mf < 2; mf++) {
                ldm_x4(ah[mf][0], ah[mf][1], ah[mf][2], ah[mf][3],
                       stb + offA + mf * (16 * RSA) + s32);
                ldm_x4(al[mf][0], al[mf][1], al[mf][2], al[mf][3],
                       stb + offA + mf * (16 * RSA) + (OFF_AL - OFF_AH) + s32);
            }
#pragma unroll
            for (int p = 0; p < 5; p++) {
                uint32_t bh0a, bh1a, bh0b, bh1b;
                uint32_t bl0a, bl1a, bl0b, bl1b;
                ldm_x4(bh0a, bh1a, bh0b, bh1b, stb + offB + p * (16 * RSA) + s32);
                ldm_x4(bl0a, bl1a, bl0b, bl1b,
                       stb + offB + p * (16 * RSA) + (OFF_BL - OFF_BH) + s32);
#pragma unroll
                for (int mf = 0; mf < 2; mf++) {
                    mma16816(acc[mf][2 * p],     ah[mf], bh0a, bh1a);
                    mma16816(acc[mf][2 * p],     ah[mf], bl0a, bl1a);
                    mma16816(acc[mf][2 * p],     al[mf], bh0a, bh1a);
                    mma16816(acc[mf][2 * p + 1], ah[mf], bh0b, bh1b);
                    mma16816(acc[mf][2 * p + 1], ah[mf], bl0b, bl1b);
                    mma16816(acc[mf][2 * p + 1], al[mf], bh0b, bh1b);
                }
            }
        }
        cp_wait0();
        __syncthreads();
    }

#pragma unroll
    for (int mf = 0; mf < 2; mf++) {
#pragma unroll
        for (int nf = 0; nf < 10; nf++) {
            int col = wn * 80 + nf * 8 + thr * 2;
            if (col >= HD) continue;
            int row0 = m0 + wm * 32 + mf * 16 + grp;
#pragma unroll
            for (int h = 0; h < 2; h++) {
                int r = row0 + h * 8;
                if (r >= M) continue;
                *(float2*)(out + (size_t)r * HD + col) =
                    make_float2(acc[mf][nf][h * 2 + 0], acc[mf][nf][h * 2 + 1]);
            }
        }
    }
}

// ---------------- conversion GEMM (MODE 0: W_i, MODE 2: W_o) ------------------
// MODE 0: A = f_bonds (K=147->160). out = acc (inp) ; outH/outL = split(relu(acc))
// MODE 2: A = concat(f_atoms, amsg) (K=433->448). out = relu(acc + bias)
template <int MODE>
__global__ __launch_bounds__(512, 1) void tc_gemm_conv(
    const float* __restrict__ A,
    const __nv_bfloat16* __restrict__ Bhi,
    const __nv_bfloat16* __restrict__ Blo,
    const float* __restrict__ amsg,
    const float* __restrict__ bias,
    float* __restrict__ out,
    __nv_bfloat16* __restrict__ outH,
    __nv_bfloat16* __restrict__ outL,
    int M)
{
    constexpr int K    = (MODE == 0) ? BF : (AF + HD);
    constexpr int NC   = (K + 31) / 32;
    constexpr int KPAD = NC * 32;

    extern __shared__ char smem[];
    const uint32_t sbase = smem_u32(smem);
    const int tid = threadIdx.x;
    const int wid = tid >> 5, lid = tid & 31;
    const int wm = wid & 3, wn = wid >> 2;
    const int grp = lid >> 2, thr = lid & 3;
    const int m0 = blockIdx.x * 128;

    const uint32_t offA = OFF_AH + (uint32_t)(wm * 32 + (lid & 15)) * RSA
                        + ((lid >> 4) & 1) * 16;
    const uint32_t offB = OFF_BH + (uint32_t)(wn * 80 + ((lid >> 4) & 1) * 8 + (lid & 7)) * RSA
                        + ((lid >> 3) & 1) * 16;

    float acc[2][10][4];
#pragma unroll
    for (int mf = 0; mf < 2; mf++)
#pragma unroll
        for (int nf = 0; nf < 10; nf++)
#pragma unroll
            for (int q = 0; q < 4; q++) acc[mf][nf][q] = 0.f;

    float fa[8];

    auto issueB = [&](int c, int buf) {
        const int k0 = c * 32;
        const uint32_t sb = sbase + buf * STAGE;
#pragma unroll
        for (int i = 0; i < 5; i++) {
            int idx = tid + i * 512;
            int half = (idx >= 1280);
            int j = half ? idx - 1280 : idx;
            int n = j >> 2, g = j & 3;
            const __nv_bfloat16* src = (half ? Blo : Bhi) + (size_t)n * KPAD + k0 + g * 8;
            cp16(sb + (half ? OFF_BL : OFF_BH) + n * RSA + g * 16, src);
        }
    };
    auto loadA = [&](int c) {
        const int k0 = c * 32;
#pragma unroll
        for (int i = 0; i < 8; i++) {
            int idx = tid + i * 512;
            int r = idx >> 5, kl = idx & 31;
            int gr = m0 + r, k = k0 + kl;
            float v = 0.f;
            if (gr < M) {
                if (MODE == 0) { if (k < BF) v = A[(size_t)gr * BF + k]; }
                else {
                    if (k < AF) v = A[(size_t)gr * AF + k];
                    else if (k < AF + HD) v = amsg[(size_t)gr * HD + (k - AF)];
                }
            }
            fa[i] = v;
        }
    };
    auto storeA = [&](int buf) {
        char* st = smem + buf * STAGE;
#pragma unroll
        for (int i = 0; i < 8; i++) {
            int idx = tid + i * 512;
            int r = idx >> 5, kl = idx & 31;
            float v = fa[i];
            __nv_bfloat16 h = __float2bfloat16(v);
            __nv_bfloat16 l = __float2bfloat16(v - __bfloat162float(h));
            *(__nv_bfloat16*)(st + OFF_AH + r * RSA + kl * 2) = h;
            *(__nv_bfloat16*)(st + OFF_AL + r * RSA + kl * 2) = l;
        }
    };

    issueB(0, 0);
    cp_commit();
    loadA(0);
    storeA(0);
    cp_wait0();
    __syncthreads();

    for (int c = 0; c < NC; c++) {
        const int cur = c & 1;
        const bool more = (c + 1 < NC);
        if (more) { issueB(c + 1, cur ^ 1); cp_commit(); loadA(c + 1); }

        const uint32_t stb = sbase + cur * STAGE;
#pragma unroll
        for (int s = 0; s < 2; s++) {
            const uint32_t s32 = s * 32;
            uint32_t ah[2][4], al[2][4];
#pragma unroll
            for (int mf = 0; mf < 2; mf++) {
                ldm_x4(ah[mf][0], ah[mf][1], ah[mf][2], ah[mf][3],
                       stb + offA + mf * (16 * RSA) + s32);
                ldm_x4(al[mf][0], al[mf][1], al[mf][2], al[mf][3],
                       stb + offA + mf * (16 * RSA) + (OFF_AL - OFF_AH) + s32);
            }
#pragma unroll
            for (int p = 0; p < 5; p++) {
                uint32_t bh0a, bh1a, bh0b, bh1b;
                uint32_t bl0a, bl1a, bl0b, bl1b;
                ldm_x4(bh0a, bh1a, bh0b, bh1b, stb + offB + p * (16 * RSA) + s32);
                ldm_x4(bl0a, bl1a, bl0b, bl1b,
                       stb + offB + p * (16 * RSA) + (OFF_BL - OFF_BH) + s32);
#pragma unroll
                for (int mf = 0; mf < 2; mf++) {
                    mma16816(acc[mf][2 * p],     ah[mf], bh0a, bh1a);
                    mma16816(acc[mf][2 * p],     ah[mf], bl0a, bl1a);
                    mma16816(acc[mf][2 * p],     al[mf], bh0a, bh1a);
                    mma16816(acc[mf][2 * p + 1], ah[mf], bh0b, bh1b);
                    mma16816(acc[mf][2 * p + 1], ah[mf], bl0b, bl1b);
                    mma16816(acc[mf][2 * p + 1], al[mf], bh0b, bh1b);
                }
            }
        }
        if (more) storeA(cur ^ 1);
        cp_wait0();
        __syncthreads();
    }

#pragma unroll
    for (int mf = 0; mf < 2; mf++) {
#pragma unroll
        for (int nf = 0; nf < 10; nf++) {
            int col = wn * 80 + nf * 8 + thr * 2;
            if (col >= HD) continue;
            int row0 = m0 + wm * 32 + mf * 16 + grp;
#pragma unroll
            for (int h = 0; h < 2; h++) {
                int r = row0 + h * 8;
                if (r >= M) continue;
                size_t o = (size_t)r * HD + col;
                float vx = acc[mf][nf][h * 2 + 0];
                float vy = acc[mf][nf][h * 2 + 1];
                if (MODE == 0) {
                    *(float2*)(out + o) = make_float2(vx, vy);
                    float rx = fmaxf(vx, 0.f), ry = fmaxf(vy, 0.f);
                    size_t ob = (size_t)r * KP + col;
                    *(uint32_t*)(outH + ob) = pack_hi(rx, ry);
                    *(uint32_t*)(outL + ob) = pack_lo(rx, ry);
                } else {
                    *(float2*)(out + o) = make_float2(fmaxf(vx + bias[col], 0.f),
                                                      fmaxf(vy + bias[col + 1], 0.f));
                }
            }
        }
    }
}

// ---------------- combine: msg' = relu(inp + aP[b2a] - P[b2revb]) -------------
__global__ void combine_kernel(const float* __restrict__ inp,
                               const float* __restrict__ P,
                               const float* __restrict__ aP,
                               const int* __restrict__ b2a,
                               const int* __restrict__ b2revb,
                               __nv_bfloat16* __restrict__ mh,
                               __nv_bfloat16* __restrict__ ml,
                               float* __restrict__ mf,
                               int out_bf16)
{
    long idx = (long)blockIdx.x * blockDim.x + threadIdx.x;
    if (idx >= (long)NBND * 75) return;
    long r = idx / 75;
    int c4 = (int)(idx % 75);
    int ia = __ldg(b2a + r), ib = __ldg(b2revb + r);
    float4 vi = *(const float4*)(inp + r * HD + c4 * 4);
    float4 va = *(const float4*)(aP + (size_t)ia * HD + c4 * 4);
    float4 vp = *(const float4*)(P  + (size_t)ib * HD + c4 * 4);
    float4 v;
    v.x = fmaxf(vi.x + va.x - vp.x, 0.f);
    v.y = fmaxf(vi.y + va.y - vp.y, 0.f);
    v.z = fmaxf(vi.z + va.z - vp.z, 0.f);
    v.w = fmaxf(vi.w + va.w - vp.w, 0.f);
    if (out_bf16) {
        size_t ob = r * KP + c4 * 4;
        uint2 h, l;
        h.x = pack_hi(v.x, v.y); h.y = pack_hi(v.z, v.w);
        l.x = pack_lo(v.x, v.y); l.y = pack_lo(v.z, v.w);
        *(uint2*)(mh + ob) = h;
        *(uint2*)(ml + ob) = l;
    } else {
        *(float4*)(mf + r * HD + c4 * 4) = v;
    }
}

// ---------------- fused prep: stats + weight split + msg pad zero -------------
__global__ void prep_kernel(const float* __restrict__ W_i,
                            const float* __restrict__ W_h,
                            const float* __restrict__ W_o)
{
    const int S1 = 320 * 160, S2 = 320 * 320, S3 = 320 * 448;
    const int WT = S1 + S2 + S3;
    long idx = (long)blockIdx.x * blockDim.x + threadIdx.x;
    if (idx < 2 * HD) {
        (&g_sum[0][0])[idx]   = 0.0;
        (&g_sumsq[0][0])[idx] = 0.0;
    }
    long t = idx - 600;
    if (t < 0) return;
    if (t < WT) {
        const float* W; __nv_bfloat16 *hi, *lo; int K, kpad;
        int ti = (int)t;
        if (ti < S1)           { W = W_i; hi = g_Bi_hi; lo = g_Bi_lo; K = BF;      kpad = 160; }
        else if (ti < S1 + S2) { ti -= S1; W = W_h; hi = g_Bh_hi; lo = g_Bh_lo; K = HD; kpad = 320; }
        else                   { ti -= S1 + S2; W = W_o; hi = g_Bo_hi; lo = g_Bo_lo; K = AF + HD; kpad = 448; }
        int n = ti / kpad, k = ti % kpad;
        float v = (n < HD && k < K) ? W[(size_t)k * HD + n] : 0.f;
        __nv_bfloat16 h = __float2bfloat16(v);
        hi[ti] = h;
        lo[ti] = __float2bfloat16(v - __bfloat162float(h));
        return;
    }
    long t2 = t - WT;                 // pad zeroing: cols 300..319 of msgH/msgL
    if (t2 >= 2L * NBND * 20) return;
    int arr = (int)(t2 / ((long)NBND * 20));
    long rem = t2 % ((long)NBND * 20);
    long r = rem / 20;
    int c = 300 + (int)(rem % 20);
    (arr ? g_msgL : g_msgH)[r * KP + c] = __float2bfloat16(0.f);
}

// ---------------- aggregation: out[i] = sum_j in[a2b[i,j]] --------------------
__global__ void agg_kernel(const float* __restrict__ src,
                           const int* __restrict__ a2b,
                           float* __restrict__ dst)
{
    int idx = blockIdx.x * blockDim.x + threadIdx.x;
    if (idx >= NATM * 75) return;
    int i = idx / 75, k4 = idx % 75;
    float4 s = {0.f, 0.f, 0.f, 0.f};
#pragma unroll
    for (int j = 0; j < MAXNB; j++) {
        int b = __ldg(a2b + i * MAXNB + j);
        float4 v = *(const float4*)(src + (size_t)b * HD + k4 * 4);
        s.x += v.x; s.y += v.y; s.z += v.z; s.w += v.w;
    }
    *(float4*)(dst + (size_t)i * HD + k4 * 4) = s;
}

// ---------------- batchnorm (two-pass, fp64 accumulation) ---------------------
__global__ void stats_kernel(const float* __restrict__ x, int rows,
                             double* __restrict__ sum, double* __restrict__ sumsq)
{
    int c = threadIdx.x;
    if (c >= HD) return;
    long r0 = (long)blockIdx.x * 512;
    long r1 = r0 + 512; if (r1 > rows) r1 = rows;
    double s = 0.0, s2 = 0.0;
    for (long r = r0; r < r1; r++) {
        double v = (double)x[(size_t)r * HD + c];
        s += v; s2 += v * v;
    }
    atomicAdd(&sum[c], s);
    atomicAdd(&sumsq[c], s2);
}

__global__ void stats_und_kernel(const float* __restrict__ msg,
                                 double* __restrict__ sum, double* __restrict__ sumsq)
{
    int c = threadIdx.x;
    if (c >= HD) return;
    long r0 = (long)blockIdx.x * 512 + 1;
    long r1 = r0 + 512; if (r1 > NUND) r1 = NUND;
    double s = 0.0, s2 = 0.0;
    for (long r = r0; r < r1; r++) {
        float v = 0.5f * (msg[(size_t)(2 * r) * HD + c] + msg[(size_t)(2 * r - 1) * HD + c]);
        double d = (double)v;
        s += d; s2 += d * d;
    }
    atomicAdd(&sum[c], s);
    atomicAdd(&sumsq[c], s2);
}

__global__ void finalize_stats(int rowsA, int rowsB,
                               const float* __restrict__ gamma,
                               const float* __restrict__ beta)
{
    int t = blockIdx.x * blockDim.x + threadIdx.x;
    if (t >= 2 * HD) return;
    int g = t / HD, c = t % HD;
    long rows = g ? rowsB : rowsA;
    double mu  = g_sum[g][c] / rows;
    double var = g_sumsq[g][c] / rows - mu * mu;
    double sc  = (double)gamma[c] / sqrt(var + 1e-5);
    g_scale[g][c] = (float)sc;
    g_shift[g][c] = beta[c] - (float)(mu * sc);
}

__global__ void norm_kernel(const float* __restrict__ x, long rows, int grp,
                            float* __restrict__ out)
{
    long idx = (long)blockIdx.x * blockDim.x + threadIdx.x;
    if (idx >= rows * 75) return;
    int c4 = (int)(idx % 75);
    float4 v  = *(const float4*)(x + idx * 4);
    float4 sc = *(const float4*)(&g_scale[grp][c4 * 4]);
    float4 sh = *(const float4*)(&g_shift[grp][c4 * 4]);
    float4 o;
    o.x = v.x * sc.x + sh.x; o.y = v.y * sc.y + sh.y;
    o.z = v.z * sc.z + sh.z; o.w = v.w * sc.w + sh.w;
    *(float4*)(out + idx * 4) = o;
}

__global__ void norm_und_kernel(const float* __restrict__ msg, float* __restrict__ out)
{
    long idx = (long)blockIdx.x * blockDim.x + threadIdx.x;
    if (idx >= (long)(NUND - 1) * 75) return;
    long r = idx / 75 + 1;
    int c4 = (int)(idx % 75);
    float4 a = *(const float4*)(msg + (size_t)(2 * r) * HD + c4 * 4);
    float4 b = *(const float4*)(msg + (size_t)(2 * r - 1) * HD + c4 * 4);
    float4 sc = *(const float4*)(&g_scale[1][c4 * 4]);
    float4 sh = *(const float4*)(&g_shift[1][c4 * 4]);
    float4 o;
    o.x = 0.5f * (a.x + b.x) * sc.x + sh.x;
    o.y = 0.5f * (a.y + b.y) * sc.y + sh.y;
    o.z = 0.5f * (a.z + b.z) * sc.z + sh.z;
    o.w = 0.5f * (a.w + b.w) * sc.w + sh.w;
    *(float4*)(out + idx * 4) = o;
}

// ---------------- launch ------------------------------------------------------
extern "C" void kernel_launch(void* const* d_in, const int* in_sizes, int n_in,
                              void* d_out, int out_size)
{
    const float* f_atoms = (const float*)d_in[0];
    const float* f_bonds = (const float*)d_in[1];
    const int*   a2b     = (const int*)  d_in[2];
    const int*   b2a     = (const int*)  d_in[3];
    const int*   b2revb  = (const int*)  d_in[4];
    const float* W_i     = (const float*)d_in[5];
    const float* W_h     = (const float*)d_in[6];
    const float* W_o     = (const float*)d_in[7];
    const float* b_o     = (const float*)d_in[8];
    const float* gamma   = (const float*)d_in[9];
    const float* beta    = (const float*)d_in[10];

    float *inp, *P, *msgF, *amsg, *hid;
    double *sum, *sumsq;
    __nv_bfloat16 *mH, *mL, *bi_h, *bi_l, *bh_h, *bh_l, *bo_h, *bo_l;
    cudaGetSymbolAddress((void**)&inp,  g_inp);
    cudaGetSymbolAddress((void**)&P,    g_P);
    cudaGetSymbolAddress((void**)&msgF, g_msgF);
    cudaGetSymbolAddress((void**)&mH,   g_msgH);
    cudaGetSymbolAddress((void**)&mL,   g_msgL);
    cudaGetSymbolAddress((void**)&amsg, g_amsg);
    cudaGetSymbolAddress((void**)&hid,  g_hid);
    cudaGetSymbolAddress((void**)&sum,  g_sum);
    cudaGetSymbolAddress((void**)&sumsq,g_sumsq);
    cudaGetSymbolAddress((void**)&bi_h, g_Bi_hi);
    cudaGetSymbolAddress((void**)&bi_l, g_Bi_lo);
    cudaGetSymbolAddress((void**)&bh_h, g_Bh_hi);
    cudaGetSymbolAddress((void**)&bh_l, g_Bh_lo);
    cudaGetSymbolAddress((void**)&bo_h, g_Bo_hi);
    cudaGetSymbolAddress((void**)&bo_l, g_Bo_lo);

    cudaFuncSetAttribute(tc_gemm_dense,  cudaFuncAttributeMaxDynamicSharedMemorySize, SMEM_TOTAL);
    cudaFuncSetAttribute(tc_gemm_conv<0>, cudaFuncAttributeMaxDynamicSharedMemorySize, SMEM_TOTAL);
    cudaFuncSetAttribute(tc_gemm_conv<2>, cudaFuncAttributeMaxDynamicSharedMemorySize, SMEM_TOTAL);

    // launches: 0 prep | 1 gemm0 | 2 dense | 3 agg | 4 combine | 5 dense (ncu -s 5)
    long prepN = 600L + 320 * (160 + 320 + 448) + 2L * NBND * 20;
    prep_kernel<<<(int)((prepN + 255) / 256), 256>>>(W_i, W_h, W_o);

    dim3 gB((NBND + 127) / 128);   // 3126
    dim3 gO((NATM + 127) / 128);   // 782
    const int AGG_G = (NATM * 75 + 255) / 256;
    const long CMB_N = (long)NBND * 75;
    const int CMB_G = (int)((CMB_N + 255) / 256);

    // inp = f_bonds @ W_i ; msg1 = relu(inp) stored as bf16 hi/lo
    tc_gemm_conv<0><<<gB, 512, SMEM_TOTAL>>>(f_bonds, bi_h, bi_l, nullptr, nullptr,
                                             inp, mH, mL, NBND);
    // iteration 1
    tc_gemm_dense<<<gB, 512, SMEM_TOTAL>>>(mH, mL, bh_h, bh_l, P, NBND);
    agg_kernel<<<AGG_G, 256>>>(P, a2b, amsg);
    combine_kernel<<<CMB_G, 256>>>(inp, P, amsg, b2a, b2revb, mH, mL, nullptr, 1);
    // iteration 2
    tc_gemm_dense<<<gB, 512, SMEM_TOTAL>>>(mH, mL, bh_h, bh_l, P, NBND);
    agg_kernel<<<AGG_G, 256>>>(P, a2b, amsg);
    combine_kernel<<<CMB_G, 256>>>(inp, P, amsg, b2a, b2revb, nullptr, nullptr, msgF, 0);
    // output transform
    agg_kernel<<<AGG_G, 256>>>(msgF, a2b, amsg);
    tc_gemm_conv<2><<<gO, 512, SMEM_TOTAL>>>(f_atoms, bo_h, bo_l, amsg, b_o,
                                             hid, nullptr, nullptr, NATM);

    stats_kernel<<<(NATM - 1 + 511) / 512, 320>>>(hid + HD, NATM - 1, sum, sumsq);
    stats_und_kernel<<<(NUND - 1 + 511) / 512, 320>>>(msgF, sum + HD, sumsq + HD);
    finalize_stats<<<(2 * HD + 255) / 256, 256>>>(NATM - 1, NUND - 1, gamma, beta);

    float* outp = (float*)d_out;
    long nAtom4 = (long)(NATM - 1) * 75;
    long nBond4 = (long)(NUND - 1) * 75;
    norm_kernel<<<(int)((nAtom4 + 255) / 256), 256>>>(hid + HD, NATM - 1, 0, outp);
    norm_und_kernel<<<(int)((nBond4 + 255) / 256), 256>>>(msgF, outp + nAtom4 * 4);
}

// round 15
// speedup vs baseline: 1.4978x; 1.1062x over previous
#include <cuda_runtime.h>
#include <cuda_bf16.h>
#include <cstdint>
#include <cstddef>

#define NBND 400001
#define NATM 100000
#define HD   300
#define AF   133
#define BF   147
#define MAXNB 6
#define NUND 200001

// ---------------- scratch ---------------------------------------------------
__device__ float g_inp [(size_t)NBND * HD];
__device__ float g_msgA[(size_t)NBND * HD];
__device__ float g_msgB[(size_t)NBND * HD];
__device__ float g_amsg[(size_t)NATM * HD];
__device__ float g_hid [(size_t)NATM * HD];
__device__ double g_sum  [2][HD];
__device__ double g_sumsq[2][HD];
__device__ float g_scale[2][HD];
__device__ float g_shift[2][HD];

// pre-split, pre-transposed weights: g_B[n][kpad] = W[k][n], bf16 hi/lo, zero pad
__device__ __nv_bfloat16 g_Bi_hi[320 * 160], g_Bi_lo[320 * 160];   // W_i K=147 ->160
__device__ __nv_bfloat16 g_Bh_hi[320 * 320], g_Bh_lo[320 * 320];   // W_h K=300 ->320
__device__ __nv_bfloat16 g_Bo_hi[320 * 448], g_Bo_lo[320 * 448];   // W_o K=433 ->448

// ---------------- helpers -----------------------------------------------------
__device__ __forceinline__ void mma16816(float* c, const uint32_t* a,
                                         uint32_t b0, uint32_t b1) {
    asm volatile(
        "mma.sync.aligned.m16n8k16.row.col.f32.bf16.bf16.f32 "
        "{%0,%1,%2,%3}, {%4,%5,%6,%7}, {%8,%9}, {%0,%1,%2,%3};"
        : "+f"(c[0]), "+f"(c[1]), "+f"(c[2]), "+f"(c[3])
        : "r"(a[0]), "r"(a[1]), "r"(a[2]), "r"(a[3]), "r"(b0), "r"(b1));
}
__device__ __forceinline__ void ldm_x4(uint32_t& r0, uint32_t& r1,
                                       uint32_t& r2, uint32_t& r3, uint32_t addr) {
    asm volatile("ldmatrix.sync.aligned.m8n8.x4.shared.b16 {%0,%1,%2,%3}, [%4];"
                 : "=r"(r0), "=r"(r1), "=r"(r2), "=r"(r3) : "r"(addr));
}
__device__ __forceinline__ uint32_t pack_hi(float x, float y) {
    __nv_bfloat16 hx = __float2bfloat16(x), hy = __float2bfloat16(y);
    return (uint32_t)__bfloat16_as_ushort(hx) | ((uint32_t)__bfloat16_as_ushort(hy) << 16);
}
__device__ __forceinline__ uint32_t pack_lo(float x, float y) {
    __nv_bfloat16 hx = __float2bfloat16(x), hy = __float2bfloat16(y);
    __nv_bfloat16 lx = __float2bfloat16(x - __bfloat162float(hx));
    __nv_bfloat16 ly = __float2bfloat16(y - __bfloat162float(hy));
    return (uint32_t)__bfloat16_as_ushort(lx) | ((uint32_t)__bfloat16_as_ushort(ly) << 16);
}
__device__ __forceinline__ uint32_t smem_u32(const void* p) {
    uint32_t a;
    asm("{ .reg .u64 t; cvta.to.shared.u64 t, %1; cvt.u32.u64 %0, t; }" : "=r"(a) : "l"(p));
    return a;
}
__device__ __forceinline__ void cp16(uint32_t dst, const void* src) {
    asm volatile("cp.async.cg.shared.global [%0], [%1], 16;" :: "r"(dst), "l"(src));
}
__device__ __forceinline__ void cp_commit() {
    asm volatile("cp.async.commit_group;" ::: "memory");
}
__device__ __forceinline__ void cp_wait0() {
    asm volatile("cp.async.wait_group 0;" ::: "memory");
}

// ---------------- HMMA GEMM --------------------------------------------------
// C[M,300] = A[M,K] @ W[K,300]; CTA tile 128x320, 512 threads, 4m x 4n warps,
// warp tile 32x80, BK=32, 2-stage cp.async double buffer, ldmatrix fragment loads.
// 3-term bf16 split: AhBh + AhBl + AlBh.
// MODE 0: A = f_bonds (K=147). out = acc
// MODE 1: A = amsg[b2a[r]] - maybe_relu(msgsrc[b2revb[r]]) (K=300). out = relu(inp+acc)
// MODE 2: A = concat(f_atoms, amsg) (K=433). out = relu(acc + bias)
constexpr int RSA = 80;                 // smem row stride bytes (40 bf16)
constexpr int OFF_AH = 0;               // 128*80 = 10240
constexpr int OFF_AL = 10240;
constexpr int OFF_BH = 20480;           // 320*80 = 25600
constexpr int OFF_BL = 46080;
constexpr int STAGE  = 71680;
constexpr int SMEM_TOTAL = 2 * STAGE;   // 143360

template <int MODE>
__global__ __launch_bounds__(512, 1) void tc_gemm(
    const float* __restrict__ A,
    const __nv_bfloat16* __restrict__ Bhi,
    const __nv_bfloat16* __restrict__ Blo,
    const float* __restrict__ inp,
    const float* __restrict__ amsg,
    const float* __restrict__ msgsrc,
    const int*   __restrict__ b2a,
    const int*   __restrict__ b2revb,
    const float* __restrict__ bias,
    float* __restrict__ out,
    int M, int relu_src)
{
    constexpr int K    = (MODE == 0) ? BF : (MODE == 1) ? HD : (AF + HD);
    constexpr int NC   = (K + 31) / 32;
    constexpr int KPAD = NC * 32;

    extern __shared__ char smem[];
    const uint32_t sbase = smem_u32(smem);
    const int tid = threadIdx.x;
    const int wid = tid >> 5, lid = tid & 31;
    const int wm = wid & 3, wn = wid >> 2;          // 4m x 4n warp grid
    const int grp = lid >> 2, thr = lid & 3;
    const int m0 = blockIdx.x * 128;

    // ldmatrix lane-address bases (within stage)
    const uint32_t offA = OFF_AH + (uint32_t)(wm * 32 + (lid & 15)) * RSA
                        + ((lid >> 4) & 1) * 16;
    const uint32_t offB = OFF_BH + (uint32_t)(wn * 80 + ((lid >> 4) & 1) * 8 + (lid & 7)) * RSA
                        + ((lid >> 3) & 1) * 16;

    // MODE1 gather pointers (4 threads per row)
    const float4* pa = nullptr; const float4* pb = nullptr;
    int rowvalid = 0;
    const int arow = tid >> 2;                 // 0..127
    const int kq   = (tid & 3) * 8;            // 0,8,16,24
    if (MODE == 1) {
        int gr = m0 + arow;
        rowvalid = (gr < M);
        int ia = rowvalid ? b2a[gr] : 0;
        int ib = rowvalid ? b2revb[gr] : 0;
        pa = (const float4*)(amsg   + (size_t)ia * HD);
        pb = (const float4*)(msgsrc + (size_t)ib * HD);
    }

    float acc[2][10][4];
#pragma unroll
    for (int mf = 0; mf < 2; mf++)
#pragma unroll
        for (int nf = 0; nf < 10; nf++)
#pragma unroll
            for (int q = 0; q < 4; q++) acc[mf][nf][q] = 0.f;

    float fa[8];   // A prefetch registers

    auto issueB = [&](int c, int buf) {
        const int k0 = c * 32;
        const uint32_t sb = sbase + buf * STAGE;
#pragma unroll
        for (int i = 0; i < 5; i++) {
            int idx = tid + i * 512;            // 2560 = 2 x 320 x 4
            int half = (idx >= 1280);
            int j = half ? idx - 1280 : idx;
            int n = j >> 2, g = j & 3;
            const __nv_bfloat16* src = (half ? Blo : Bhi) + (size_t)n * KPAD + k0 + g * 8;
            cp16(sb + (half ? OFF_BL : OFF_BH) + n * RSA + g * 16, src);
        }
    };
    auto loadA = [&](int c) {
        const int k0 = c * 32;
        if (MODE == 1) {
#pragma unroll
            for (int j = 0; j < 2; j++) {
                int k = k0 + kq + j * 4;
                float4 v = {0.f, 0.f, 0.f, 0.f};
                if (rowvalid && k + 3 < HD) {
                    float4 x = pa[k >> 2], y = pb[k >> 2];
                    if (relu_src) {
                        y.x = fmaxf(y.x, 0.f); y.y = fmaxf(y.y, 0.f);
                        y.z = fmaxf(y.z, 0.f); y.w = fmaxf(y.w, 0.f);
                    }
                    v.x = x.x - y.x; v.y = x.y - y.y; v.z = x.z - y.z; v.w = x.w - y.w;
                }
                fa[j * 4 + 0] = v.x; fa[j * 4 + 1] = v.y;
                fa[j * 4 + 2] = v.z; fa[j * 4 + 3] = v.w;
            }
        } else {
#pragma unroll
            for (int i = 0; i < 8; i++) {
                int idx = tid + i * 512;        // 128*32 = 4096
                int r = idx >> 5, kl = idx & 31;
                int gr = m0 + r, k = k0 + kl;
                float v = 0.f;
                if (gr < M) {
                    if (MODE == 0) { if (k < BF) v = A[(size_t)gr * BF + k]; }
                    else {
                        if (k < AF) v = A[(size_t)gr * AF + k];
                        else if (k < AF + HD) v = amsg[(size_t)gr * HD + (k - AF)];
                    }
                }
                fa[i] = v;
            }
        }
    };
    auto storeA = [&](int buf) {
        char* st = smem + buf * STAGE;
        if (MODE == 1) {
            char* dh = st + OFF_AH + arow * RSA + kq * 2;
            char* dl = st + OFF_AL + arow * RSA + kq * 2;
#pragma unroll
            for (int j = 0; j < 4; j++) {
                float x = fa[j * 2], y = fa[j * 2 + 1];
                *(uint32_t*)(dh + j * 4) = pack_hi(x, y);
                *(uint32_t*)(dl + j * 4) = pack_lo(x, y);
            }
        } else {
#pragma unroll
            for (int i = 0; i < 8; i++) {
                int idx = tid + i * 512;
                int r = idx >> 5, kl = idx & 31;
                float v = fa[i];
                __nv_bfloat16 h = __float2bfloat16(v);
                __nv_bfloat16 l = __float2bfloat16(v - __bfloat162float(h));
                *(__nv_bfloat16*)(st + OFF_AH + r * RSA + kl * 2) = h;
                *(__nv_bfloat16*)(st + OFF_AL + r * RSA + kl * 2) = l;
            }
        }
    };

    // prologue
    issueB(0, 0);
    cp_commit();
    loadA(0);
    storeA(0);
    cp_wait0();
    __syncthreads();

    for (int c = 0; c < NC; c++) {
        const int cur = c & 1;
        const bool more = (c + 1 < NC);
        if (more) { issueB(c + 1, cur ^ 1); cp_commit(); loadA(c + 1); }

        const uint32_t stb = sbase + cur * STAGE;
#pragma unroll
        for (int s = 0; s < 2; s++) {
            const uint32_t s32 = s * 32;
            uint32_t ah[2][4], al[2][4];
#pragma unroll
            for (int mf = 0; mf < 2; mf++) {
                ldm_x4(ah[mf][0], ah[mf][1], ah[mf][2], ah[mf][3],
                       stb + offA + mf * (16 * RSA) + s32);
                ldm_x4(al[mf][0], al[mf][1], al[mf][2], al[mf][3],
                       stb + offA + mf * (16 * RSA) + (OFF_AL - OFF_AH) + s32);
            }
#pragma unroll
            for (int p = 0; p < 5; p++) {
                uint32_t bh0a, bh1a, bh0b, bh1b;
                uint32_t bl0a, bl1a, bl0b, bl1b;
                ldm_x4(bh0a, bh1a, bh0b, bh1b, stb + offB + p * (16 * RSA) + s32);
                ldm_x4(bl0a, bl1a, bl0b, bl1b,
                       stb + offB + p * (16 * RSA) + (OFF_BL - OFF_BH) + s32);
#pragma unroll
                for (int mf = 0; mf < 2; mf++) {
                    mma16816(acc[mf][2 * p],     ah[mf], bh0a, bh1a);
                    mma16816(acc[mf][2 * p],     ah[mf], bl0a, bl1a);
                    mma16816(acc[mf][2 * p],     al[mf], bh0a, bh1a);
                    mma16816(acc[mf][2 * p + 1], ah[mf], bh0b, bh1b);
                    mma16816(acc[mf][2 * p + 1], ah[mf], bl0b, bl1b);
                    mma16816(acc[mf][2 * p + 1], al[mf], bh0b, bh1b);
                }
            }
        }
        if (more) storeA(cur ^ 1);
        cp_wait0();
        __syncthreads();
    }

    // ---- epilogue ----
#pragma unroll
    for (int mf = 0; mf < 2; mf++) {
#pragma unroll
        for (int nf = 0; nf < 10; nf++) {
            int col = wn * 80 + nf * 8 + thr * 2;
            if (col >= HD) continue;
            int row0 = m0 + wm * 32 + mf * 16 + grp;
#pragma unroll
            for (int h = 0; h < 2; h++) {
                int r = row0 + h * 8;
                if (r >= M) continue;
                size_t o = (size_t)r * HD + col;
                float vx = acc[mf][nf][h * 2 + 0];
                float vy = acc[mf][nf][h * 2 + 1];
                if (MODE == 0) {
                    *(float2*)(out + o) = make_float2(vx, vy);
                } else if (MODE == 1) {
                    float2 p = *(const float2*)(inp + o);
                    *(float2*)(out + o) = make_float2(fmaxf(p.x + vx, 0.f),
                                                      fmaxf(p.y + vy, 0.f));
                } else {
                    *(float2*)(out + o) = make_float2(fmaxf(vx + bias[col], 0.f),
                                                      fmaxf(vy + bias[col + 1], 0.f));
                }
            }
        }
    }
}

// ---------------- fused prep: zero stats + split/transpose all weights --------
__global__ void prep_kernel(const float* __restrict__ W_i,
                            const float* __restrict__ W_h,
                            const float* __restrict__ W_o)
{
    const int S1 = 320 * 160, S2 = 320 * 320, S3 = 320 * 448;
    int idx = blockIdx.x * blockDim.x + threadIdx.x;
    if (idx < 2 * HD) {
        (&g_sum[0][0])[idx]   = 0.0;
        (&g_sumsq[0][0])[idx] = 0.0;
    }
    int t = idx - 600;
    if (t < 0) return;
    const float* W; __nv_bfloat16 *hi, *lo; int K, kpad;
    if (t < S1)            { W = W_i; hi = g_Bi_hi; lo = g_Bi_lo; K = BF;      kpad = 160; }
    else if (t < S1 + S2)  { t -= S1; W = W_h; hi = g_Bh_hi; lo = g_Bh_lo; K = HD; kpad = 320; }
    else if (t < S1+S2+S3) { t -= S1 + S2; W = W_o; hi = g_Bo_hi; lo = g_Bo_lo; K = AF + HD; kpad = 448; }
    else return;
    int n = t / kpad, k = t % kpad;
    float v = (n < HD && k < K) ? W[(size_t)k * HD + n] : 0.f;
    __nv_bfloat16 h = __float2bfloat16(v);
    hi[t] = h;
    lo[t] = __float2bfloat16(v - __bfloat162float(h));
}

// ---------------- aggregation -------------------------------------------------
__global__ void agg_kernel(const float* __restrict__ msg,
                           const int* __restrict__ a2b,
                           float* __restrict__ amsg, int do_relu)
{
    int idx = blockIdx.x * blockDim.x + threadIdx.x;
    if (idx >= NATM * 75) return;
    int i = idx / 75, k4 = idx % 75;
    float4 s = {0.f, 0.f, 0.f, 0.f};
#pragma unroll
    for (int j = 0; j < MAXNB; j++) {
        int b = __ldg(a2b + i * MAXNB + j);
        float4 v = *(const float4*)(msg + (size_t)b * HD + k4 * 4);
        if (do_relu) {
            v.x = fmaxf(v.x, 0.f); v.y = fmaxf(v.y, 0.f);
            v.z = fmaxf(v.z, 0.f); v.w = fmaxf(v.w, 0.f);
        }
        s.x += v.x; s.y += v.y; s.z += v.z; s.w += v.w;
    }
    *(float4*)(amsg + (size_t)i * HD + k4 * 4) = s;
}

// ---------------- batchnorm (two-pass, fp64 accumulation) ---------------------
// 128 rows per block (4x more blocks than before -> MLP/occupancy bound fix)
__global__ void stats_kernel(const float* __restrict__ x, int rows,
                             double* __restrict__ sum, double* __restrict__ sumsq)
{
    int c = threadIdx.x;
    if (c >= HD) return;
    long r0 = (long)blockIdx.x * 128;
    long r1 = r0 + 128; if (r1 > rows) r1 = rows;
    double s = 0.0, s2 = 0.0;
    for (long r = r0; r < r1; r++) {
        double v = (double)x[(size_t)r * HD + c];
        s += v; s2 += v * v;
    }
    atomicAdd(&sum[c], s);
    atomicAdd(&sumsq[c], s2);
}

__global__ void stats_und_kernel(const float* __restrict__ msg,
                                 double* __restrict__ sum, double* __restrict__ sumsq)
{
    int c = threadIdx.x;
    if (c >= HD) return;
    long r0 = (long)blockIdx.x * 128 + 1;
    long r1 = r0 + 128; if (r1 > NUND) r1 = NUND;
    double s = 0.0, s2 = 0.0;
    for (long r = r0; r < r1; r++) {
        float v = 0.5f * (msg[(size_t)(2 * r) * HD + c] + msg[(size_t)(2 * r - 1) * HD + c]);
        double d = (double)v;
        s += d; s2 += d * d;
    }
    atomicAdd(&sum[c], s);
    atomicAdd(&sumsq[c], s2);
}

__global__ void finalize_stats(int rowsA, int rowsB,
                               const float* __restrict__ gamma,
                               const float* __restrict__ beta)
{
    int t = blockIdx.x * blockDim.x + threadIdx.x;
    if (t >= 2 * HD) return;
    int g = t / HD, c = t % HD;
    long rows = g ? rowsB : rowsA;
    double mu  = g_sum[g][c] / rows;
    double var = g_sumsq[g][c] / rows - mu * mu;
    double sc  = (double)gamma[c] / sqrt(var + 1e-5);
    g_scale[g][c] = (float)sc;
    g_shift[g][c] = beta[c] - (float)(mu * sc);
}

__global__ void norm_kernel(const float* __restrict__ x, long rows, int grp,
                            float* __restrict__ out)
{
    long idx = (long)blockIdx.x * blockDim.x + threadIdx.x;
    if (idx >= rows * 75) return;
    int c4 = (int)(idx % 75);
    float4 v  = *(const float4*)(x + idx * 4);
    float4 sc = *(const float4*)(&g_scale[grp][c4 * 4]);
    float4 sh = *(const float4*)(&g_shift[grp][c4 * 4]);
    float4 o;
    o.x = v.x * sc.x + sh.x; o.y = v.y * sc.y + sh.y;
    o.z = v.z * sc.z + sh.z; o.w = v.w * sc.w + sh.w;
    *(float4*)(out + idx * 4) = o;
}

__global__ void norm_und_kernel(const float* __restrict__ msg, float* __restrict__ out)
{
    long idx = (long)blockIdx.x * blockDim.x + threadIdx.x;
    if (idx >= (long)(NUND - 1) * 75) return;
    long r = idx / 75 + 1;
    int c4 = (int)(idx % 75);
    float4 a = *(const float4*)(msg + (size_t)(2 * r) * HD + c4 * 4);
    float4 b = *(const float4*)(msg + (size_t)(2 * r - 1) * HD + c4 * 4);
    float4 sc = *(const float4*)(&g_scale[1][c4 * 4]);
    float4 sh = *(const float4*)(&g_shift[1][c4 * 4]);
    float4 o;
    o.x = 0.5f * (a.x + b.x) * sc.x + sh.x;
    o.y = 0.5f * (a.y + b.y) * sc.y + sh.y;
    o.z = 0.5f * (a.z + b.z) * sc.z + sh.z;
    o.w = 0.5f * (a.w + b.w) * sc.w + sh.w;
    *(float4*)(out + idx * 4) = o;
}

// ---------------- launch ------------------------------------------------------
extern "C" void kernel_launch(void* const* d_in, const int* in_sizes, int n_in,
                              void* d_out, int out_size)
{
    const float* f_atoms = (const float*)d_in[0];
    const float* f_bonds = (const float*)d_in[1];
    const int*   a2b     = (const int*)  d_in[2];
    const int*   b2a     = (const int*)  d_in[3];
    const int*   b2revb  = (const int*)  d_in[4];
    const float* W_i     = (const float*)d_in[5];
    const float* W_h     = (const float*)d_in[6];
    const float* W_o     = (const float*)d_in[7];
    const float* b_o     = (const float*)d_in[8];
    const float* gamma   = (const float*)d_in[9];
    const float* beta    = (const float*)d_in[10];

    float *inp, *msgA, *msgB, *amsg, *hid;
    double *sum, *sumsq;
    __nv_bfloat16 *bi_h, *bi_l, *bh_h, *bh_l, *bo_h, *bo_l;
    cudaGetSymbolAddress((void**)&inp,  g_inp);
    cudaGetSymbolAddress((void**)&msgA, g_msgA);
    cudaGetSymbolAddress((void**)&msgB, g_msgB);
    cudaGetSymbolAddress((void**)&amsg, g_amsg);
    cudaGetSymbolAddress((void**)&hid,  g_hid);
    cudaGetSymbolAddress((void**)&sum,  g_sum);
    cudaGetSymbolAddress((void**)&sumsq,g_sumsq);
    cudaGetSymbolAddress((void**)&bi_h, g_Bi_hi);
    cudaGetSymbolAddress((void**)&bi_l, g_Bi_lo);
    cudaGetSymbolAddress((void**)&bh_h, g_Bh_hi);
    cudaGetSymbolAddress((void**)&bh_l, g_Bh_lo);
    cudaGetSymbolAddress((void**)&bo_h, g_Bo_hi);
    cudaGetSymbolAddress((void**)&bo_l, g_Bo_lo);

    cudaFuncSetAttribute(tc_gemm<0>, cudaFuncAttributeMaxDynamicSharedMemorySize, SMEM_TOTAL);
    cudaFuncSetAttribute(tc_gemm<1>, cudaFuncAttributeMaxDynamicSharedMemorySize, SMEM_TOTAL);
    cudaFuncSetAttribute(tc_gemm<2>, cudaFuncAttributeMaxDynamicSharedMemorySize, SMEM_TOTAL);

    // launches: 0 prep | 1 gemm0 | 2 agg | 3 gemm1 | 4 agg | 5 gemm1 (ncu -s 5)
    prep_kernel<<<(600 + 320 * (160 + 320 + 448) + 255) / 256, 256>>>(W_i, W_h, W_o);

    dim3 gB((NBND + 127) / 128);   // 3126
    dim3 gO((NATM + 127) / 128);   // 782
    const int AGG_G = (NATM * 75 + 255) / 256;

    tc_gemm<0><<<gB, 512, SMEM_TOTAL>>>(f_bonds, bi_h, bi_l, nullptr, nullptr, nullptr,
                                        nullptr, nullptr, nullptr, inp, NBND, 0);
    agg_kernel<<<AGG_G, 256>>>(inp, a2b, amsg, 1);
    tc_gemm<1><<<gB, 512, SMEM_TOTAL>>>(nullptr, bh_h, bh_l, inp, amsg, inp,
                                        b2a, b2revb, nullptr, msgB, NBND, 1);
    agg_kernel<<<AGG_G, 256>>>(msgB, a2b, amsg, 0);
    tc_gemm<1><<<gB, 512, SMEM_TOTAL>>>(nullptr, bh_h, bh_l, inp, amsg, msgB,
                                        b2a, b2revb, nullptr, msgA, NBND, 0);
    agg_kernel<<<AGG_G, 256>>>(msgA, a2b, amsg, 0);
    tc_gemm<2><<<gO, 512, SMEM_TOTAL>>>(f_atoms, bo_h, bo_l, nullptr, amsg, nullptr,
                                        nullptr, nullptr, b_o, hid, NATM, 0);

    stats_kernel<<<(NATM - 1 + 127) / 128, 320>>>(hid + HD, NATM - 1, sum, sumsq);
    stats_und_kernel<<<(NUND - 1 + 127) / 128, 320>>>(msgA, sum + HD, sumsq + HD);
    finalize_stats<<<(2 * HD + 255) / 256, 256>>>(NATM - 1, NUND - 1, gamma, beta);

    float* outp = (float*)d_out;
    long nAtom4 = (long)(NATM - 1) * 75;
    long nBond4 = (long)(NUND - 1) * 75;
    norm_kernel<<<(int)((nAtom4 + 255) / 256), 256>>>(hid + HD, NATM - 1, 0, outp);
    norm_und_kernel<<<(int)((nBond4 + 255) / 256), 256>>>(msgA, outp + nAtom4 * 4);
}